// round 1
// baseline (speedup 1.0000x reference)
#include <cuda_runtime.h>
#include <cstdint>

// Problem shape (fixed by the dataset)
#define Bv 256
#define Mv 1024
#define Dv 128
#define Nv 26
#define EP 32   // padded per-row stride for the emission scratch

// ---------------- scratch (static device globals; no allocation) ----------------
__device__ float g_e[(size_t)Bv * Mv * EP];     // 32 MB emission scores, padded
__device__ float g_pF[Bv * EP];                 // forward message at i=511
__device__ float g_pB[Bv * EP];                 // backward message at i=511
__device__ float g_sF[Bv], g_sB[Bv];            // log-scales
__device__ float g_uF[Bv], g_uB[Bv];            // unnormalized score halves

// packed fp32x2 FMA (sm_100+/sm_103a)
__device__ __forceinline__ void ffma2(unsigned long long &d,
                                      unsigned long long a,
                                      unsigned long long b) {
    asm("fma.rn.f32x2 %0, %1, %2, %0;" : "+l"(d) : "l"(a), "l"(b));
}

// ---------------- Kernel 1: emissions e = X @ W^T  ----------------
// One thread per (b,m) row; 26 fp32x2 accumulators; W in shared (broadcast LDS.128).
// Stores staged through shared so the padded-stride global write is coalesced.
__global__ void __launch_bounds__(128) emis_kernel(const float* __restrict__ X,
                                                   const float* __restrict__ W) {
    __shared__ alignas(16) float sW[Nv * Dv];      // 13 KB
    __shared__ float sOut[128 * 33];               // 16.9 KB, +1 pad vs banks
    const int tid = threadIdx.x;

    for (int i = tid; i < Nv * Dv; i += 128) sW[i] = W[i];
    __syncthreads();

    const size_t row = (size_t)blockIdx.x * 128 + tid;
    const ulonglong2* __restrict__ Xv =
        reinterpret_cast<const ulonglong2*>(X + row * Dv);
    const ulonglong2* __restrict__ Wv =
        reinterpret_cast<const ulonglong2*>(sW);

    unsigned long long acc[Nv];
#pragma unroll
    for (int a = 0; a < Nv; a++) acc[a] = 0ull;

#pragma unroll 4
    for (int d4 = 0; d4 < Dv / 4; d4++) {
        const ulonglong2 x2 = Xv[d4];
#pragma unroll
        for (int a = 0; a < Nv; a++) {
            const ulonglong2 w2 = Wv[a * (Dv / 4) + d4];
            ffma2(acc[a], x2.x, w2.x);
            ffma2(acc[a], x2.y, w2.y);
        }
    }

#pragma unroll
    for (int a = 0; a < Nv; a++) {
        const float lo = __uint_as_float((unsigned)(acc[a] & 0xffffffffull));
        const float hi = __uint_as_float((unsigned)(acc[a] >> 32));
        sOut[tid * 33 + a] = lo + hi;
    }
#pragma unroll
    for (int a = Nv; a < 32; a++) sOut[tid * 33 + a] = 0.0f;
    __syncthreads();

    const size_t base = (size_t)blockIdx.x * 128 * EP;
    for (int idx = tid; idx < 128 * 32; idx += 128) {
        g_e[base + idx] = sOut[(idx >> 5) * 33 + (idx & 31)];
    }
}

// ---------------- Kernel 2: forward/backward scan ----------------
// One block per sequence; warp 0 runs forward to i=511, warp 1 runs backward to i=511.
// Lane a holds f[a] (or beta[a]); expT column/row held in 26 registers per lane.
// Rescale every 8 steps (warp max + log) keeps fp32 in range.
__global__ void __launch_bounds__(64) scan_kernel(const int* __restrict__ labels,
                                                  const float* __restrict__ T) {
    const int s    = blockIdx.x;
    const int warp = threadIdx.x >> 5;
    const int lane = threadIdx.x & 31;
    const unsigned FULL = 0xffffffffu;

    const float* __restrict__ eseq = g_e + (size_t)s * Mv * EP + lane;
    const int*   __restrict__ lab  = labels + s * Mv;

    float expT[Nv];

    if (warp == 0) {
        // -------- forward: f_0 = exp(e_0); f_i = expE_i * (expT^T f_{i-1}) --------
#pragma unroll
        for (int b = 0; b < Nv; b++)
            expT[b] = (lane < Nv) ? __expf(__ldg(&T[b * Nv + lane])) : 0.0f;

        const float e0 = eseq[0];
        float f = (lane < Nv) ? __expf(e0) : 0.0f;
        const int y0 = __ldg(&lab[0]);
        float un = __shfl_sync(FULL, e0, y0);
        int yprev = y0;
        float ls = 0.0f;

        float ep1 = eseq[EP], ep2 = eseq[2 * EP];
        int   yp1 = __ldg(&lab[1]), yp2 = __ldg(&lab[2]);

        for (int i = 1; i <= 511; i++) {
            const float ee = ep1;
            const int   y  = yp1;
            ep1 = ep2;  yp1 = yp2;
            ep2 = eseq[(i + 2) * EP];          // i+2 <= 513 < 1024, safe
            yp2 = __ldg(&lab[i + 2]);

            const float expE = __expf(ee);
            un += __shfl_sync(FULL, ee, y) + __ldg(&T[yprev * Nv + y]);
            yprev = y;

            float a0 = 0.f, a1 = 0.f, a2 = 0.f, a3 = 0.f;
#pragma unroll
            for (int b = 0; b < 24; b += 4) {
                a0 = fmaf(__shfl_sync(FULL, f, b + 0), expT[b + 0], a0);
                a1 = fmaf(__shfl_sync(FULL, f, b + 1), expT[b + 1], a1);
                a2 = fmaf(__shfl_sync(FULL, f, b + 2), expT[b + 2], a2);
                a3 = fmaf(__shfl_sync(FULL, f, b + 3), expT[b + 3], a3);
            }
            a0 = fmaf(__shfl_sync(FULL, f, 24), expT[24], a0);
            a1 = fmaf(__shfl_sync(FULL, f, 25), expT[25], a1);
            f = ((a0 + a1) + (a2 + a3)) * expE;

            if ((i & 7) == 0) {
                float v = (lane < Nv) ? f : 0.0f;
#pragma unroll
                for (int o = 16; o; o >>= 1)
                    v = fmaxf(v, __shfl_xor_sync(FULL, v, o));
                f = __fdividef(f, v);
                ls += logf(v);
            }
        }
        g_pF[s * EP + lane] = f;
        if (lane == 0) { g_sF[s] = ls; g_uF[s] = un; }
    } else {
        // -------- backward: beta_1023 = 1; beta_i = expT (expE_{i+1} .* beta_{i+1}) ----
#pragma unroll
        for (int a = 0; a < Nv; a++)
            expT[a] = (lane < Nv) ? __expf(__ldg(&T[lane * Nv + a])) : 0.0f;

        float bta = (lane < Nv) ? 1.0f : 0.0f;
        float ls = 0.0f, un = 0.0f;

        float ep1 = eseq[1023 * EP], ep2 = eseq[1022 * EP];
        int ynext = __ldg(&lab[1023]);
        int yc1   = __ldg(&lab[1022]);
        int yc2   = __ldg(&lab[1021]);

        for (int i = 1022; i >= 511; i--) {
            const float ee = ep1;           // e row i+1
            const int y_ip1 = ynext;
            const int y_i   = yc1;
            ep1 = ep2;
            ep2 = eseq[(i - 1) * EP];       // i-1 >= 510, safe
            ynext = y_i;
            yc1 = yc2;
            yc2 = __ldg(&lab[i - 2]);       // i-2 >= 509, safe

            const float expE = __expf(ee);
            un += __shfl_sync(FULL, ee, y_ip1) + __ldg(&T[y_i * Nv + y_ip1]);

            const float h = expE * bta;
            float a0 = 0.f, a1 = 0.f, a2 = 0.f, a3 = 0.f;
#pragma unroll
            for (int a = 0; a < 24; a += 4) {
                a0 = fmaf(__shfl_sync(FULL, h, a + 0), expT[a + 0], a0);
                a1 = fmaf(__shfl_sync(FULL, h, a + 1), expT[a + 1], a1);
                a2 = fmaf(__shfl_sync(FULL, h, a + 2), expT[a + 2], a2);
                a3 = fmaf(__shfl_sync(FULL, h, a + 3), expT[a + 3], a3);
            }
            a0 = fmaf(__shfl_sync(FULL, h, 24), expT[24], a0);
            a1 = fmaf(__shfl_sync(FULL, h, 25), expT[25], a1);
            bta = (a0 + a1) + (a2 + a3);

            if ((i & 7) == 0) {
                float v = (lane < Nv) ? bta : 0.0f;
#pragma unroll
                for (int o = 16; o; o >>= 1)
                    v = fmaxf(v, __shfl_xor_sync(FULL, v, o));
                bta = __fdividef(bta, v);
                ls += logf(v);
            }
        }
        g_pB[s * EP + lane] = bta;
        if (lane == 0) { g_sB[s] = ls; g_uB[s] = un; }
    }
}

// ---------------- Kernel 3: combine halves and reduce mean ----------------
__global__ void __launch_bounds__(256) combine_kernel(float* __restrict__ out) {
    __shared__ float red[256];
    const int s = threadIdx.x;

    float z = 0.0f;
#pragma unroll
    for (int b = 0; b < Nv; b++)
        z += g_pF[s * EP + b] * g_pB[s * EP + b];

    const float lp = g_uF[s] + g_uB[s] - (logf(z) + g_sF[s] + g_sB[s]);
    red[s] = lp;
    __syncthreads();
#pragma unroll
    for (int o = 128; o; o >>= 1) {
        if (s < o) red[s] += red[s + o];
        __syncthreads();
    }
    if (s == 0) out[0] = red[0] * (1.0f / Bv);
}

// ---------------- entry point ----------------
extern "C" void kernel_launch(void* const* d_in, const int* in_sizes, int n_in,
                              void* d_out, int out_size) {
    const float* X      = (const float*)d_in[0];   // [B, M, D] f32
    const int*   labels = (const int*)  d_in[1];   // [B, M] i32
    const float* W      = (const float*)d_in[2];   // [N, D] f32
    const float* T      = (const float*)d_in[3];   // [N, N] f32
    float* out = (float*)d_out;

    emis_kernel<<<(Bv * Mv) / 128, 128>>>(X, W);
    scan_kernel<<<Bv, 64>>>(labels, T);
    combine_kernel<<<1, 256>>>(out);
}

// round 2
// speedup vs baseline: 1.6918x; 1.6918x over previous
#include <cuda_runtime.h>
#include <cstdint>

// Problem shape (fixed by the dataset)
#define Bv 256
#define Mv 1024
#define Dv 128
#define Nv 26
#define EP 32   // padded per-row stride for the emission scratch

// ---------------- scratch (static device globals; no allocation) ----------------
__device__ float g_e[(size_t)Bv * Mv * EP];     // 32 MB emission scores, padded
__device__ float g_pF[Bv * EP];                 // forward message at i=512
__device__ float g_pB[Bv * EP];                 // backward message at i=512
__device__ float g_sF[Bv], g_sB[Bv];            // log-scales
__device__ float g_uF[Bv], g_uB[Bv];            // unnormalized score halves

// packed fp32x2 FMA (sm_100+/sm_103a)
__device__ __forceinline__ void ffma2(unsigned long long &d,
                                      unsigned long long a,
                                      unsigned long long b) {
    asm("fma.rn.f32x2 %0, %1, %2, %0;" : "+l"(d) : "l"(a), "l"(b));
}

// ---------------- Kernel 1: emissions e = X @ W^T  ----------------
// 256 rows per block. X staged through shared in 4 K-chunks of 32 dims
// (coalesced float4 loads), W resident in shared, 26 fp32x2 accumulators
// per thread. Output staged through shared (reusing the X tile) so the
// padded-stride global write is coalesced.
__global__ void __launch_bounds__(256, 3) emis_kernel(const float* __restrict__ X,
                                                      const float* __restrict__ W) {
    __shared__ alignas(16) float sW[Nv * Dv];      // 13 KB
    __shared__ alignas(16) float sX[256 * 36];     // 36 KB: 256 rows x (32 + 4 pad)
    const int tid = threadIdx.x;

    for (int i = tid; i < Nv * Dv / 4; i += 256)
        reinterpret_cast<float4*>(sW)[i] = reinterpret_cast<const float4*>(W)[i];

    unsigned long long acc[Nv];
#pragma unroll
    for (int a = 0; a < Nv; a++) acc[a] = 0ull;

    const size_t row0 = (size_t)blockIdx.x * 256;
    const float4* __restrict__ Xv = reinterpret_cast<const float4*>(X) + row0 * 32;
    const ulonglong2* __restrict__ Wv = reinterpret_cast<const ulonglong2*>(sW);

#pragma unroll
    for (int c = 0; c < 4; c++) {
        __syncthreads();   // sW ready (c==0) / previous chunk's reads done (c>0)
#pragma unroll
        for (int p = 0; p < 8; p++) {
            const int r = (tid >> 3) + (p << 5);
            const int q = tid & 7;
            reinterpret_cast<float4*>(sX)[r * 9 + q] = Xv[(size_t)r * 32 + c * 8 + q];
        }
        __syncthreads();

        const ulonglong2* __restrict__ xrow =
            reinterpret_cast<const ulonglong2*>(sX + tid * 36);
#pragma unroll
        for (int q = 0; q < 8; q++) {
            const ulonglong2 x2 = xrow[q];
#pragma unroll
            for (int a = 0; a < Nv; a++) {
                const ulonglong2 w2 = Wv[a * 32 + c * 8 + q];
                ffma2(acc[a], x2.x, w2.x);
                ffma2(acc[a], x2.y, w2.y);
            }
        }
    }

    // epilogue: stage results in sX (now free), then coalesced global store
    __syncthreads();
#pragma unroll
    for (int a = 0; a < Nv; a++) {
        const float lo = __uint_as_float((unsigned)(acc[a] & 0xffffffffull));
        const float hi = __uint_as_float((unsigned)(acc[a] >> 32));
        sX[tid * 33 + a] = lo + hi;
    }
#pragma unroll
    for (int a = Nv; a < 32; a++) sX[tid * 33 + a] = 0.0f;
    __syncthreads();

    const size_t base = (size_t)blockIdx.x * 256 * EP;
    for (int idx = tid; idx < 256 * 32; idx += 256)
        g_e[base + idx] = sX[(idx >> 5) * 33 + (idx & 31)];
}

// ---------------- Kernel 2: forward/backward scan ----------------
static __device__ __forceinline__ float crf_matvec(float fv, const float* expT) {
    const unsigned FULL = 0xffffffffu;
    float a0 = 0.f, a1 = 0.f, a2 = 0.f, a3 = 0.f;
#pragma unroll
    for (int b = 0; b < 24; b += 4) {
        a0 = fmaf(__shfl_sync(FULL, fv, b + 0), expT[b + 0], a0);
        a1 = fmaf(__shfl_sync(FULL, fv, b + 1), expT[b + 1], a1);
        a2 = fmaf(__shfl_sync(FULL, fv, b + 2), expT[b + 2], a2);
        a3 = fmaf(__shfl_sync(FULL, fv, b + 3), expT[b + 3], a3);
    }
    a0 = fmaf(__shfl_sync(FULL, fv, 24), expT[24], a0);
    a1 = fmaf(__shfl_sync(FULL, fv, 25), expT[25], a1);
    return (a0 + a1) + (a2 + a3);
}

// Exact power-of-two rescale: one redux.max + exponent arithmetic.
static __device__ __forceinline__ void rescale(float &v, float &ls) {
    const unsigned mb = __reduce_max_sync(0xffffffffu, __float_as_uint(v));
    const unsigned pb = mb & 0x7f800000u;                 // 2^(E-127)
    v *= __uint_as_float(0x7f000000u - pb);               // exact * 2^(127-E)
    ls += (float)((int)(pb >> 23) - 127) * 0.6931471805599453f;
}

// One block = 2 sequences x 2 directions = 4 warps (one per SMSP).
__global__ void __launch_bounds__(128) scan_kernel(const int* __restrict__ labels,
                                                   const float* __restrict__ T) {
    const int warp = threadIdx.x >> 5;
    const int lane = threadIdx.x & 31;
    const int s    = blockIdx.x * 2 + (warp >> 1);
    const int dir  = warp & 1;
    const unsigned FULL = 0xffffffffu;

    const float* __restrict__ eseq = g_e + (size_t)s * Mv * EP + lane;
    const int*   __restrict__ lab  = labels + s * Mv;

    float expT[Nv];
    float ep[8];
    int   yq[8];

    if (dir == 0) {
        // forward: f_0 = exp(e_0); f_i = expE_i * (expT^T f_{i-1}); 512 steps
#pragma unroll
        for (int b = 0; b < Nv; b++)
            expT[b] = (lane < Nv) ? __expf(__ldg(&T[b * Nv + lane])) : 0.0f;

        const float e0 = eseq[0];
        float f = (lane < Nv) ? __expf(e0) : 0.0f;
        int yprev = __ldg(&lab[0]);
        float un = __shfl_sync(FULL, e0, yprev);
        float ls = 0.0f;

#pragma unroll
        for (int k = 0; k < 8; k++) {
            ep[k] = eseq[(size_t)(1 + k) * EP];
            yq[k] = __ldg(&lab[1 + k]);
        }

        for (int i0 = 1; i0 <= 505; i0 += 8) {
#pragma unroll
            for (int j = 0; j < 8; j++) {
                const int i = i0 + j;
                const float ee = ep[j];
                const int   y  = yq[j];
                ep[j] = eseq[(size_t)(i + 8) * EP];      // i+8 <= 520 < 1024
                yq[j] = __ldg(&lab[i + 8]);

                const float expE = __expf(ee);
                un += __shfl_sync(FULL, ee, y) + __ldg(&T[yprev * Nv + y]);
                yprev = y;

                f = crf_matvec(f, expT) * expE;
                if (j == 7) rescale(f, ls);
            }
        }
        g_pF[s * EP + lane] = f;
        if (lane == 0) { g_sF[s] = ls; g_uF[s] = un; }
    } else {
        // backward: beta_1023 = 1; beta_i = expT (expE_{i+1} .* beta_{i+1}); i=1022..512
#pragma unroll
        for (int a = 0; a < Nv; a++)
            expT[a] = (lane < Nv) ? __expf(__ldg(&T[lane * Nv + a])) : 0.0f;

        float bta = (lane < Nv) ? 1.0f : 0.0f;
        float ls = 0.0f, un = 0.0f;
        int ynext = __ldg(&lab[1023]);

#pragma unroll
        for (int k = 0; k < 8; k++) {
            ep[k] = eseq[(size_t)(1023 - k) * EP];   // e_{i+1} for i = 1022-k
            yq[k] = __ldg(&lab[1022 - k]);           // y_i    for i = 1022-k
        }

        // prologue: 7 steps, i = 1022 .. 1016 (slots 0..6)
#pragma unroll
        for (int j = 0; j < 7; j++) {
            const int i = 1022 - j;
            const float ee = ep[j];
            const int   yi = yq[j];
            ep[j] = eseq[(size_t)(i - 7) * EP];      // e_{(i-8)+1}
            yq[j] = __ldg(&lab[i - 8]);

            const float expE = __expf(ee);
            un += __shfl_sync(FULL, ee, ynext) + __ldg(&T[yi * Nv + ynext]);
            ynext = yi;

            bta = crf_matvec(expE * bta, expT);
            if (j == 6) rescale(bta, ls);
        }

        // main: 63 groups of 8, i = 1015 .. 512 (slot = (j+7)&7)
        for (int i0 = 1015; i0 >= 519; i0 -= 8) {
#pragma unroll
            for (int j = 0; j < 8; j++) {
                const int sl = (j + 7) & 7;
                const int i = i0 - j;
                const float ee = ep[sl];
                const int   yi = yq[sl];
                ep[sl] = eseq[(size_t)(i - 7) * EP]; // min row 505
                yq[sl] = __ldg(&lab[i - 8]);         // min idx 504

                const float expE = __expf(ee);
                un += __shfl_sync(FULL, ee, ynext) + __ldg(&T[yi * Nv + ynext]);
                ynext = yi;

                bta = crf_matvec(expE * bta, expT);
                if (j == 7) rescale(bta, ls);
            }
        }
        g_pB[s * EP + lane] = bta;
        if (lane == 0) { g_sB[s] = ls; g_uB[s] = un; }
    }
}

// ---------------- Kernel 3: combine halves and reduce mean ----------------
__global__ void __launch_bounds__(256) combine_kernel(float* __restrict__ out) {
    __shared__ float red[256];
    const int s = threadIdx.x;

    float z = 0.0f;
#pragma unroll
    for (int b = 0; b < Nv; b++)
        z += g_pF[s * EP + b] * g_pB[s * EP + b];

    const float lp = g_uF[s] + g_uB[s] - (logf(z) + g_sF[s] + g_sB[s]);
    red[s] = lp;
    __syncthreads();
#pragma unroll
    for (int o = 128; o; o >>= 1) {
        if (s < o) red[s] += red[s + o];
        __syncthreads();
    }
    if (s == 0) out[0] = red[0] * (1.0f / Bv);
}

// ---------------- entry point ----------------
extern "C" void kernel_launch(void* const* d_in, const int* in_sizes, int n_in,
                              void* d_out, int out_size) {
    const float* X      = (const float*)d_in[0];   // [B, M, D] f32
    const int*   labels = (const int*)  d_in[1];   // [B, M] i32
    const float* W      = (const float*)d_in[2];   // [N, D] f32
    const float* T      = (const float*)d_in[3];   // [N, N] f32
    float* out = (float*)d_out;

    emis_kernel<<<(Bv * Mv) / 256, 256>>>(X, W);
    scan_kernel<<<Bv / 2, 128>>>(labels, T);
    combine_kernel<<<1, 256>>>(out);
}

// round 3
// speedup vs baseline: 2.4191x; 1.4299x over previous
#include <cuda_runtime.h>
#include <cstdint>

#define Bv 256
#define Mv 1024
#define Dv 128
#define Nv 26
#define EP 32   // padded per-row stride for emission scratch

// ---------------- scratch ----------------
__device__ float g_e[(size_t)Bv * Mv * EP];     // 32 MB emissions, padded
__device__ float g_pF[Bv * EP];                 // fwd pre-emission vec at i=512
__device__ float g_pB[Bv * EP];                 // bwd post-emission vec at i=512
__device__ float g_sF[Bv], g_sB[Bv];            // log-scales
__device__ float g_u[Bv];                       // unnormalized path scores

__device__ __forceinline__ void ffma2(unsigned long long &d,
                                      unsigned long long a,
                                      unsigned long long b) {
    asm("fma.rn.f32x2 %0, %1, %2, %0;" : "+l"(d) : "l"(a), "l"(b));
}
__device__ __forceinline__ unsigned long long packf2(float lo, float hi) {
    unsigned long long r;
    asm("mov.b64 %0, {%1, %2};" : "=l"(r) : "f"(lo), "f"(hi));
    return r;
}

// ---------------- Kernel 1: emissions e = X @ W^T ----------------
// 256 rows/block, K in 8 chunks of 16 dims. X transposed into shared
// (conflict-free stride-258), then held in registers for the whole label
// loop. W loads batched 4-wide per label for MLP.
__global__ void __launch_bounds__(256, 2) emis_kernel(const float* __restrict__ X,
                                                      const float* __restrict__ W) {
    __shared__ alignas(16) float sW[Nv * Dv];      // 13 KB
    __shared__ alignas(16) float sB[256 * 33];     // 33.8 KB (>= 16*258 transpose buf)
    const int tid = threadIdx.x;

    for (int i = tid; i < Nv * Dv / 4; i += 256)
        reinterpret_cast<float4*>(sW)[i] = reinterpret_cast<const float4*>(W)[i];

    unsigned long long acc[Nv];
#pragma unroll
    for (int a = 0; a < Nv; a++) acc[a] = 0ull;

    const size_t row0 = (size_t)blockIdx.x * 256;
    const float4* __restrict__ Xv = reinterpret_cast<const float4*>(X) + row0 * 32;
    const ulonglong2* __restrict__ Wv2 = reinterpret_cast<const ulonglong2*>(sW);
    const int rb = tid >> 2, c4 = tid & 3;

#pragma unroll 1
    for (int c = 0; c < 8; c++) {
        __syncthreads();
        // transpose-load 16-dim chunk: coalesced LDG.128, conflict-free scalar STS
#pragma unroll
        for (int p = 0; p < 4; p++) {
            const int rr = rb + p * 64;
            const float4 v = __ldcs(&Xv[(size_t)rr * 32 + c * 4 + c4]);
            sB[(4 * c4 + 0) * 258 + rr] = v.x;
            sB[(4 * c4 + 1) * 258 + rr] = v.y;
            sB[(4 * c4 + 2) * 258 + rr] = v.z;
            sB[(4 * c4 + 3) * 258 + rr] = v.w;
        }
        __syncthreads();

        // this thread's 16 x-values into registers (lane-consecutive, no conflicts)
        unsigned long long xp[8];
#pragma unroll
        for (int q = 0; q < 8; q++)
            xp[q] = packf2(sB[(2 * q) * 258 + tid], sB[(2 * q + 1) * 258 + tid]);

#pragma unroll
        for (int a = 0; a < Nv; a++) {
            const int wb = a * 32 + c * 4;
            const ulonglong2 w0 = Wv2[wb + 0];
            const ulonglong2 w1 = Wv2[wb + 1];
            const ulonglong2 w2 = Wv2[wb + 2];
            const ulonglong2 w3 = Wv2[wb + 3];
            ffma2(acc[a], xp[0], w0.x);  ffma2(acc[a], xp[1], w0.y);
            ffma2(acc[a], xp[2], w1.x);  ffma2(acc[a], xp[3], w1.y);
            ffma2(acc[a], xp[4], w2.x);  ffma2(acc[a], xp[5], w2.y);
            ffma2(acc[a], xp[6], w3.x);  ffma2(acc[a], xp[7], w3.y);
        }
    }

    // epilogue: stage in shared, coalesced padded-stride store
    __syncthreads();
#pragma unroll
    for (int a = 0; a < Nv; a++) {
        const float lo = __uint_as_float((unsigned)(acc[a] & 0xffffffffull));
        const float hi = __uint_as_float((unsigned)(acc[a] >> 32));
        sB[tid * 33 + a] = lo + hi;
    }
#pragma unroll
    for (int a = Nv; a < 32; a++) sB[tid * 33 + a] = 0.0f;
    __syncthreads();

    const size_t base = (size_t)blockIdx.x * 256 * EP;
    for (int idx = tid; idx < 256 * 32; idx += 256)
        g_e[base + idx] = sB[(idx >> 5) * 33 + (idx & 31)];
}

// ---------------- Kernel 2: fwd/bwd scan + parallel unnorm gather ----------------
// Block = 192 threads: warps 0-3 scan (2 seqs x 2 dirs), warps 4-5 unnorm gather.
// f vector lives in shared (ping-pong); matvec = 7 broadcast LDS.128 + 26 FMA.
static __device__ __forceinline__ float mv26(const float* fb, const float* expT) {
    const float4* q = reinterpret_cast<const float4*>(fb);
    const float4 q0 = q[0], q1 = q[1], q2 = q[2], q3 = q[3], q4 = q[4], q5 = q[5], q6 = q[6];
    float a0 = q0.x * expT[0];
    float a1 = q0.y * expT[1];
    float a2 = q0.z * expT[2];
    float a3 = q0.w * expT[3];
    a0 = fmaf(q1.x, expT[4], a0);  a1 = fmaf(q1.y, expT[5], a1);
    a2 = fmaf(q1.z, expT[6], a2);  a3 = fmaf(q1.w, expT[7], a3);
    a0 = fmaf(q2.x, expT[8], a0);  a1 = fmaf(q2.y, expT[9], a1);
    a2 = fmaf(q2.z, expT[10], a2); a3 = fmaf(q2.w, expT[11], a3);
    a0 = fmaf(q3.x, expT[12], a0); a1 = fmaf(q3.y, expT[13], a1);
    a2 = fmaf(q3.z, expT[14], a2); a3 = fmaf(q3.w, expT[15], a3);
    a0 = fmaf(q4.x, expT[16], a0); a1 = fmaf(q4.y, expT[17], a1);
    a2 = fmaf(q4.z, expT[18], a2); a3 = fmaf(q4.w, expT[19], a3);
    a0 = fmaf(q5.x, expT[20], a0); a1 = fmaf(q5.y, expT[21], a1);
    a2 = fmaf(q5.z, expT[22], a2); a3 = fmaf(q5.w, expT[23], a3);
    a0 = fmaf(q6.x, expT[24], a0); a1 = fmaf(q6.y, expT[25], a1);
    return (a0 + a1) + (a2 + a3);
}

__global__ void __launch_bounds__(192) scan_kernel(const int* __restrict__ labels,
                                                   const float* __restrict__ T) {
    __shared__ alignas(16) float fbuf[4][2][32];
    const int warp = threadIdx.x >> 5;
    const int lane = threadIdx.x & 31;
    const unsigned FULL = 0xffffffffu;

    if (warp >= 4) {
        // -------- unnorm gather warps: fully parallel over positions --------
        const int s = blockIdx.x * 2 + (warp - 4);
        const int* __restrict__ lab = labels + s * Mv;
        const float* __restrict__ eb = g_e + (size_t)s * Mv * EP;
        float un = 0.0f;
#pragma unroll 4
        for (int k = 0; k < 32; k++) {
            const int i = k * 32 + lane;
            const int y = __ldg(&lab[i]);
            float t = __ldg(&eb[(size_t)i * EP + y]);
            if (i < Mv - 1)
                t += __ldg(&T[y * Nv + __ldg(&lab[i + 1])]);
            un += t;
        }
#pragma unroll
        for (int o = 16; o; o >>= 1) un += __shfl_xor_sync(FULL, un, o);
        if (lane == 0) g_u[s] = un;
        return;
    }

    // -------- scan warps --------
    const int s   = blockIdx.x * 2 + (warp >> 1);
    const int dir = warp & 1;
    const float* __restrict__ eseq = g_e + (size_t)s * Mv * EP + lane;
    float* const fb0 = fbuf[warp][0];
    float* const fb1 = fbuf[warp][1];

    float expT[Nv];
    float ep[8];
    float carry = 1.0f;
    int   eAcc = 0;
    float msum = 0.0f;

    if (dir == 0) {
        // forward: stored vec = alpha_i; 512 steps (i=1..512); output mv at i=512
#pragma unroll
        for (int b = 0; b < Nv; b++)
            expT[b] = (lane < Nv) ? __expf(__ldg(&T[b * Nv + lane])) : 0.0f;

        const float e0 = eseq[0];
        fb0[lane] = (lane < Nv) ? __expf(e0) : 0.0f;
        __syncwarp();
#pragma unroll
        for (int k = 0; k < 8; k++) ep[k] = eseq[(size_t)(1 + k) * EP];

        int p = 0;
        float fn = 0.0f;
        for (int g = 0; g < 64; g++) {
#pragma unroll
            for (int j = 0; j < 8; j++) {
                const int i = 1 + g * 8 + j;
                const float ee = ep[j];
                ep[j] = eseq[(size_t)(i + 8) * EP];
                const float expE = __expf(ee) * carry;
                carry = 1.0f;
                const float* src = p ? fb1 : fb0;
                float*       dst = p ? fb0 : fb1;
                msum = mv26(src, expT);
                fn = (lane < Nv) ? msum * expE : 0.0f;
                dst[lane] = fn;
                __syncwarp();
                p ^= 1;
            }
            if (g != 63) {
                const unsigned mb = __reduce_max_sync(FULL, __float_as_uint(fn));
                const unsigned pb = mb & 0x7f800000u;
                carry = __uint_as_float(0x7f000000u - pb);   // 2^(127-E), exact
                eAcc += (int)(pb >> 23) - 127;
            }
        }
        g_pF[s * EP + lane] = (lane < Nv) ? msum : 0.0f;     // pre-emission u_512
        if (lane == 0) g_sF[s] = (float)eAcc * 0.6931471805599453f;
    } else {
        // backward in h-form: h_1023 = expE_1023; h_i = expE_i * (Texp h_{i+1});
        // 511 steps (i = 1022..512); output h_512.
#pragma unroll
        for (int a = 0; a < Nv; a++)
            expT[a] = (lane < Nv) ? __expf(__ldg(&T[lane * Nv + a])) : 0.0f;

        const float e1023 = eseq[(size_t)1023 * EP];
        fb0[lane] = (lane < Nv) ? __expf(e1023) : 0.0f;
        __syncwarp();
#pragma unroll
        for (int k = 0; k < 8; k++) ep[k] = eseq[(size_t)(1022 - k) * EP];

        int p = 0;
        float fn = 0.0f;
        // prologue: 7 steps, i = 1022..1016 (slots 0..6)
#pragma unroll
        for (int j = 0; j < 7; j++) {
            const int i = 1022 - j;
            const float ee = ep[j];
            ep[j] = eseq[(size_t)(i - 8) * EP];
            const float expE = __expf(ee);
            const float* src = p ? fb1 : fb0;
            float*       dst = p ? fb0 : fb1;
            fn = (lane < Nv) ? mv26(src, expT) * expE : 0.0f;
            dst[lane] = fn;
            __syncwarp();
            p ^= 1;
        }
        {
            const unsigned mb = __reduce_max_sync(FULL, __float_as_uint(fn));
            const unsigned pb = mb & 0x7f800000u;
            carry = __uint_as_float(0x7f000000u - pb);
            eAcc += (int)(pb >> 23) - 127;
        }
        // 63 groups of 8: i = 1015 .. 512
        for (int g = 0; g < 63; g++) {
#pragma unroll
            for (int j = 0; j < 8; j++) {
                const int i = 1015 - g * 8 - j;
                const int sl = (j + 7) & 7;
                const float ee = ep[sl];
                ep[sl] = eseq[(size_t)(i - 8) * EP];
                const float expE = __expf(ee) * carry;
                carry = 1.0f;
                const float* src = p ? fb1 : fb0;
                float*       dst = p ? fb0 : fb1;
                fn = (lane < Nv) ? mv26(src, expT) * expE : 0.0f;
                dst[lane] = fn;
                __syncwarp();
                p ^= 1;
            }
            if (g != 62) {
                const unsigned mb = __reduce_max_sync(FULL, __float_as_uint(fn));
                const unsigned pb = mb & 0x7f800000u;
                carry = __uint_as_float(0x7f000000u - pb);
                eAcc += (int)(pb >> 23) - 127;
            }
        }
        g_pB[s * EP + lane] = fn;                            // h_512
        if (lane == 0) g_sB[s] = (float)eAcc * 0.6931471805599453f;
    }
}

// ---------------- Kernel 3: combine ----------------
__global__ void __launch_bounds__(256) combine_kernel(float* __restrict__ out) {
    __shared__ float red[256];
    const int s = threadIdx.x;

    float z = 0.0f;
#pragma unroll
    for (int b = 0; b < Nv; b++)
        z += g_pF[s * EP + b] * g_pB[s * EP + b];

    red[s] = g_u[s] - (logf(z) + g_sF[s] + g_sB[s]);
    __syncthreads();
#pragma unroll
    for (int o = 128; o; o >>= 1) {
        if (s < o) red[s] += red[s + o];
        __syncthreads();
    }
    if (s == 0) out[0] = red[0] * (1.0f / Bv);
}

// ---------------- entry point ----------------
extern "C" void kernel_launch(void* const* d_in, const int* in_sizes, int n_in,
                              void* d_out, int out_size) {
    const float* X      = (const float*)d_in[0];
    const int*   labels = (const int*)  d_in[1];
    const float* W      = (const float*)d_in[2];
    const float* T      = (const float*)d_in[3];
    float* out = (float*)d_out;

    emis_kernel<<<(Bv * Mv) / 256, 256>>>(X, W);
    scan_kernel<<<Bv / 2, 192>>>(labels, T);
    combine_kernel<<<1, 256>>>(out);
}

// round 4
// speedup vs baseline: 2.9758x; 1.2301x over previous
#include <cuda_runtime.h>
#include <cstdint>

#define Bv 256
#define Mv 1024
#define Dv 128
#define Nv 26
#define EP 32   // padded per-row stride for emission scratch

// ---------------- scratch ----------------
__device__ float g_e[(size_t)Bv * Mv * EP];     // 32 MB emissions, padded
__device__ float g_pF[Bv * EP];                 // fwd pre-emission vec at i=512
__device__ float g_pB[Bv * EP];                 // bwd post-emission vec at i=512
__device__ float g_sF[Bv], g_sB[Bv];            // log-scales
__device__ float g_u[Bv];                       // unnormalized path scores

// ---------------- Kernel 1: emissions e = X @ W^T via HMMA bf16 ----------------
// Block: 256 threads (8 warps) computes 128 rows x 32 labels (W zero-padded).
// X tile converted fp32->bf16 into smem (row stride 136 bf16 = 272 B, bank-safe),
// W converted once per block. Each warp: 16 rows, 8 k-steps x 4 n-tiles of
// mma.sync.m16n8k16.
__global__ void __launch_bounds__(256) emis_kernel(const float* __restrict__ X,
                                                   const float* __restrict__ W) {
    __shared__ __align__(16) unsigned short sX[128 * 136];   // 34816 B
    __shared__ __align__(16) unsigned short sW[32 * 136];    //  8704 B
    const int tid  = threadIdx.x;
    const int warp = tid >> 5, lane = tid & 31;
    const int g = lane >> 2, t = lane & 3;

    // W: 26x128 fp32 -> bf16 (1664 float2), zero-pad labels 26..31
    for (int i = tid; i < 1664; i += 256) {
        const float2 w2 = reinterpret_cast<const float2*>(W)[i];
        const int row = i >> 6;           // 64 float2 per row
        const int cp  = i & 63;
        unsigned u;
        asm("cvt.rn.bf16x2.f32 %0, %1, %2;" : "=r"(u) : "f"(w2.y), "f"(w2.x));
        *reinterpret_cast<unsigned*>(&sW[row * 136 + cp * 2]) = u;
    }
    for (int i = tid; i < 6 * 68; i += 256)
        *reinterpret_cast<unsigned*>(&sW[26 * 136 + i * 2]) = 0;

    // X tile: 128 rows x 128 dims, coalesced float4 -> two bf16x2
    const float4* __restrict__ Xv =
        reinterpret_cast<const float4*>(X) + (size_t)blockIdx.x * 128 * 32;
    for (int i = tid; i < 128 * 32; i += 256) {
        const float4 v = Xv[i];
        const int row = i >> 5, q = i & 31;
        unsigned u0, u1;
        asm("cvt.rn.bf16x2.f32 %0, %1, %2;" : "=r"(u0) : "f"(v.y), "f"(v.x));
        asm("cvt.rn.bf16x2.f32 %0, %1, %2;" : "=r"(u1) : "f"(v.w), "f"(v.z));
        *reinterpret_cast<uint2*>(&sX[row * 136 + q * 4]) = make_uint2(u0, u1);
    }
    __syncthreads();

    // compute
    float d[4][4];
#pragma unroll
    for (int n = 0; n < 4; n++)
#pragma unroll
        for (int r = 0; r < 4; r++) d[n][r] = 0.0f;

    const unsigned* sXu = reinterpret_cast<const unsigned*>(sX);
    const unsigned* sWu = reinterpret_cast<const unsigned*>(sW);
    const int arow  = 16 * warp + g;
    const int abase = (arow * 272 + t * 4) >> 2;   // uint index

#pragma unroll
    for (int k = 0; k < 8; k++) {
        // A frags: row g(+8), dims k*16 + 2t (+8)
        const unsigned a0 = sXu[abase + k * 8];
        const unsigned a1 = sXu[abase + k * 8 + 544];   // +8 rows (2176 B)
        const unsigned a2 = sXu[abase + k * 8 + 4];     // +8 dims (16 B)
        const unsigned a3 = sXu[abase + k * 8 + 548];
#pragma unroll
        for (int n = 0; n < 4; n++) {
            // B frags: label n*8+g, dims k*16 + 2t (+8)
            const int bbase = ((n * 8 + g) * 272 + k * 32 + t * 4) >> 2;
            const unsigned b0 = sWu[bbase];
            const unsigned b1 = sWu[bbase + 4];
            asm volatile(
                "mma.sync.aligned.m16n8k16.row.col.f32.bf16.bf16.f32 "
                "{%0,%1,%2,%3}, {%4,%5,%6,%7}, {%8,%9}, {%0,%1,%2,%3};"
                : "+f"(d[n][0]), "+f"(d[n][1]), "+f"(d[n][2]), "+f"(d[n][3])
                : "r"(a0), "r"(a1), "r"(a2), "r"(a3), "r"(b0), "r"(b1));
        }
    }

    // epilogue: D[g][2t,2t+1] / D[g+8][...] -> padded g_e (sector-aligned STG.64)
    float* eout = g_e + (size_t)blockIdx.x * 128 * EP;
    const int r0 = 16 * warp + g;
#pragma unroll
    for (int n = 0; n < 4; n++) {
        const int c = n * 8 + 2 * t;
        *reinterpret_cast<float2*>(&eout[(size_t)r0 * 32 + c]) =
            make_float2(d[n][0], d[n][1]);
        *reinterpret_cast<float2*>(&eout[(size_t)(r0 + 8) * 32 + c]) =
            make_float2(d[n][2], d[n][3]);
    }
}

// ---------------- Kernel 2: fwd/bwd scan + parallel unnorm gather ----------------
// f lives in registers (lane a holds f[a]); matvec via 26 pipelined shuffles.
// Padding lanes (26..31) carry exact zeros via expT==0 -> no per-step predication.
static __device__ __forceinline__ float mv26s(float fv, const float* expT) {
    const unsigned FULL = 0xffffffffu;
    float a0, a1, a2, a3;
    a0 = __shfl_sync(FULL, fv, 0) * expT[0];
    a1 = __shfl_sync(FULL, fv, 1) * expT[1];
    a2 = __shfl_sync(FULL, fv, 2) * expT[2];
    a3 = __shfl_sync(FULL, fv, 3) * expT[3];
#pragma unroll
    for (int b = 4; b < 24; b += 4) {
        a0 = fmaf(__shfl_sync(FULL, fv, b + 0), expT[b + 0], a0);
        a1 = fmaf(__shfl_sync(FULL, fv, b + 1), expT[b + 1], a1);
        a2 = fmaf(__shfl_sync(FULL, fv, b + 2), expT[b + 2], a2);
        a3 = fmaf(__shfl_sync(FULL, fv, b + 3), expT[b + 3], a3);
    }
    a0 = fmaf(__shfl_sync(FULL, fv, 24), expT[24], a0);
    a1 = fmaf(__shfl_sync(FULL, fv, 25), expT[25], a1);
    return (a0 + a1) + (a2 + a3);
}

__global__ void __launch_bounds__(192) scan_kernel(const int* __restrict__ labels,
                                                   const float* __restrict__ T) {
    const int warp = threadIdx.x >> 5;
    const int lane = threadIdx.x & 31;
    const unsigned FULL = 0xffffffffu;

    if (warp >= 4) {
        // unnorm gather: fully parallel over positions
        const int s = blockIdx.x * 2 + (warp - 4);
        const int* __restrict__ lab = labels + s * Mv;
        const float* __restrict__ eb = g_e + (size_t)s * Mv * EP;
        float un = 0.0f;
#pragma unroll 4
        for (int k = 0; k < 32; k++) {
            const int i = k * 32 + lane;
            const int y = __ldg(&lab[i]);
            float v = __ldg(&eb[(size_t)i * EP + y]);
            if (i < Mv - 1)
                v += __ldg(&T[y * Nv + __ldg(&lab[i + 1])]);
            un += v;
        }
#pragma unroll
        for (int o = 16; o; o >>= 1) un += __shfl_xor_sync(FULL, un, o);
        if (lane == 0) g_u[s] = un;
        return;
    }

    const int s   = blockIdx.x * 2 + (warp >> 1);
    const int dir = warp & 1;
    const float* __restrict__ eseq = g_e + (size_t)s * Mv * EP + lane;

    float expT[Nv];
    float ep[8];
    float carry = 1.0f;
    int   eAcc = 0;

    if (dir == 0) {
        // forward: f_i = expE_i * (expT^T f_{i-1}); i = 1..512; keep pre-emission msum
#pragma unroll
        for (int b = 0; b < Nv; b++)
            expT[b] = (lane < Nv) ? __expf(__ldg(&T[b * Nv + lane])) : 0.0f;

        const float e0 = eseq[0];
        float f = (lane < Nv) ? __expf(e0) : 0.0f;
#pragma unroll
        for (int k = 0; k < 8; k++) ep[k] = eseq[(size_t)(1 + k) * EP];

        float msum = 0.0f;
        for (int gi = 0; gi < 64; gi++) {
#pragma unroll
            for (int j = 0; j < 8; j++) {
                const int i = 1 + gi * 8 + j;
                const float ee = ep[j];
                ep[j] = eseq[(size_t)(i + 8) * EP];      // i+8 <= 520 < 1024
                const float expE = __expf(ee) * carry;
                carry = 1.0f;
                msum = mv26s(f, expT);
                f = msum * expE;
            }
            if (gi != 63) {
                const unsigned mb = __reduce_max_sync(FULL, __float_as_uint(f));
                const unsigned pb = mb & 0x7f800000u;
                carry = __uint_as_float(0x7f000000u - pb);   // exact 2^(127-E)
                eAcc += (int)(pb >> 23) - 127;
            }
        }
        g_pF[s * EP + lane] = msum;                          // pre-emission u_512
        if (lane == 0) g_sF[s] = (float)eAcc * 0.6931471805599453f;
    } else {
        // backward (h-form): h_1023 = expE_1023; h_i = expE_i * (expT h_{i+1}); i=1022..512
#pragma unroll
        for (int a = 0; a < Nv; a++)
            expT[a] = (lane < Nv) ? __expf(__ldg(&T[lane * Nv + a])) : 0.0f;

        const float e1023 = eseq[(size_t)1023 * EP];
        float h = (lane < Nv) ? __expf(e1023) : 0.0f;
#pragma unroll
        for (int k = 0; k < 8; k++) ep[k] = eseq[(size_t)(1022 - k) * EP];

        // prologue: 7 steps, i = 1022..1016 (slots 0..6)
#pragma unroll
        for (int j = 0; j < 7; j++) {
            const int i = 1022 - j;
            const float ee = ep[j];
            ep[j] = eseq[(size_t)(i - 8) * EP];
            const float expE = __expf(ee);
            h = mv26s(h, expT) * expE;
        }
        {
            const unsigned mb = __reduce_max_sync(FULL, __float_as_uint(h));
            const unsigned pb = mb & 0x7f800000u;
            carry = __uint_as_float(0x7f000000u - pb);
            eAcc += (int)(pb >> 23) - 127;
        }
        // 63 groups of 8: i = 1015..512
        for (int gi = 0; gi < 63; gi++) {
#pragma unroll
            for (int j = 0; j < 8; j++) {
                const int i = 1015 - gi * 8 - j;
                const int sl = (j + 7) & 7;
                const float ee = ep[sl];
                ep[sl] = eseq[(size_t)(i - 8) * EP];     // min row 504
                const float expE = __expf(ee) * carry;
                carry = 1.0f;
                h = mv26s(h, expT) * expE;
            }
            if (gi != 62) {
                const unsigned mb = __reduce_max_sync(FULL, __float_as_uint(h));
                const unsigned pb = mb & 0x7f800000u;
                carry = __uint_as_float(0x7f000000u - pb);
                eAcc += (int)(pb >> 23) - 127;
            }
        }
        g_pB[s * EP + lane] = h;                             // h_512
        if (lane == 0) g_sB[s] = (float)eAcc * 0.6931471805599453f;
    }
}

// ---------------- Kernel 3: combine ----------------
__global__ void __launch_bounds__(256) combine_kernel(float* __restrict__ out) {
    __shared__ float red[256];
    const int s = threadIdx.x;

    float z = 0.0f;
#pragma unroll
    for (int b = 0; b < Nv; b++)
        z += g_pF[s * EP + b] * g_pB[s * EP + b];

    red[s] = g_u[s] - (logf(z) + g_sF[s] + g_sB[s]);
    __syncthreads();
#pragma unroll
    for (int o = 128; o; o >>= 1) {
        if (s < o) red[s] += red[s + o];
        __syncthreads();
    }
    if (s == 0) out[0] = red[0] * (1.0f / Bv);
}

// ---------------- entry point ----------------
extern "C" void kernel_launch(void* const* d_in, const int* in_sizes, int n_in,
                              void* d_out, int out_size) {
    const float* X      = (const float*)d_in[0];
    const int*   labels = (const int*)  d_in[1];
    const float* W      = (const float*)d_in[2];
    const float* T      = (const float*)d_in[3];
    float* out = (float*)d_out;

    emis_kernel<<<(Bv * Mv) / 128, 256>>>(X, W);
    scan_kernel<<<Bv / 2, 192>>>(labels, T);
    combine_kernel<<<1, 256>>>(out);
}

// round 5
// speedup vs baseline: 3.6091x; 1.2128x over previous
#include <cuda_runtime.h>
#include <cuda_bf16.h>
#include <cstdint>

#define Bv 256
#define Mv 1024
#define Dv 128
#define Nv 26
#define EP 32   // padded per-row stride for emission scratch

// ---------------- scratch ----------------
__device__ __nv_bfloat16 g_e[(size_t)Bv * Mv * EP];   // 16 MB emissions (bf16, padded)
__device__ float g_pF[Bv * EP];                 // fwd pre-emission vec at i=512
__device__ float g_pB[Bv * EP];                 // bwd post-emission vec at i=512
__device__ float g_sF[Bv], g_sB[Bv];            // log-scales
__device__ float g_u[Bv];                       // unnormalized path scores

__device__ __forceinline__ void ffma2(unsigned long long &d,
                                      unsigned long long a,
                                      unsigned long long b) {
    asm("fma.rn.f32x2 %0, %1, %2, %0;" : "+l"(d) : "l"(a), "l"(b));
}
__device__ __forceinline__ void fadd2(unsigned long long &d, unsigned long long a) {
    asm("add.rn.f32x2 %0, %0, %1;" : "+l"(d) : "l"(a));
}
__device__ __forceinline__ unsigned long long packf2(float lo, float hi) {
    unsigned long long r;
    asm("mov.b64 %0, {%1, %2};" : "=l"(r) : "f"(lo), "f"(hi));
    return r;
}

// ---------------- Kernel 1: emissions e = X @ W^T via HMMA bf16 ----------------
__global__ void __launch_bounds__(256) emis_kernel(const float* __restrict__ X,
                                                   const float* __restrict__ W) {
    __shared__ __align__(16) unsigned short sX[128 * 136];   // 34816 B
    __shared__ __align__(16) unsigned short sW[32 * 136];    //  8704 B
    const int tid  = threadIdx.x;
    const int warp = tid >> 5, lane = tid & 31;
    const int g = lane >> 2, t = lane & 3;

    // W: 26x128 fp32 -> bf16, zero-pad labels 26..31
    for (int i = tid; i < 1664; i += 256) {
        const float2 w2 = reinterpret_cast<const float2*>(W)[i];
        const int row = i >> 6;
        const int cp  = i & 63;
        unsigned u;
        asm("cvt.rn.bf16x2.f32 %0, %1, %2;" : "=r"(u) : "f"(w2.y), "f"(w2.x));
        *reinterpret_cast<unsigned*>(&sW[row * 136 + cp * 2]) = u;
    }
    for (int i = tid; i < 6 * 68; i += 256)
        *reinterpret_cast<unsigned*>(&sW[26 * 136 + i * 2]) = 0;

    // X tile: 128 rows x 128 dims, coalesced float4 -> two bf16x2
    const float4* __restrict__ Xv =
        reinterpret_cast<const float4*>(X) + (size_t)blockIdx.x * 128 * 32;
    for (int i = tid; i < 128 * 32; i += 256) {
        const float4 v = __ldcs(&Xv[i]);
        const int row = i >> 5, q = i & 31;
        unsigned u0, u1;
        asm("cvt.rn.bf16x2.f32 %0, %1, %2;" : "=r"(u0) : "f"(v.y), "f"(v.x));
        asm("cvt.rn.bf16x2.f32 %0, %1, %2;" : "=r"(u1) : "f"(v.w), "f"(v.z));
        *reinterpret_cast<uint2*>(&sX[row * 136 + q * 4]) = make_uint2(u0, u1);
    }
    __syncthreads();

    float d[4][4];
#pragma unroll
    for (int n = 0; n < 4; n++)
#pragma unroll
        for (int r = 0; r < 4; r++) d[n][r] = 0.0f;

    const unsigned* sXu = reinterpret_cast<const unsigned*>(sX);
    const unsigned* sWu = reinterpret_cast<const unsigned*>(sW);
    const int arow  = 16 * warp + g;
    const int abase = (arow * 272 + t * 4) >> 2;

#pragma unroll
    for (int k = 0; k < 8; k++) {
        const unsigned a0 = sXu[abase + k * 8];
        const unsigned a1 = sXu[abase + k * 8 + 544];
        const unsigned a2 = sXu[abase + k * 8 + 4];
        const unsigned a3 = sXu[abase + k * 8 + 548];
#pragma unroll
        for (int n = 0; n < 4; n++) {
            const int bbase = ((n * 8 + g) * 272 + k * 32 + t * 4) >> 2;
            const unsigned b0 = sWu[bbase];
            const unsigned b1 = sWu[bbase + 4];
            asm volatile(
                "mma.sync.aligned.m16n8k16.row.col.f32.bf16.bf16.f32 "
                "{%0,%1,%2,%3}, {%4,%5,%6,%7}, {%8,%9}, {%0,%1,%2,%3};"
                : "+f"(d[n][0]), "+f"(d[n][1]), "+f"(d[n][2]), "+f"(d[n][3])
                : "r"(a0), "r"(a1), "r"(a2), "r"(a3), "r"(b0), "r"(b1));
        }
    }

    // epilogue: convert to bf16x2 and store (4B/lane per n-tile per row-half)
    unsigned short* eout =
        reinterpret_cast<unsigned short*>(g_e) + (size_t)blockIdx.x * 128 * EP;
    const int r0 = 16 * warp + g;
#pragma unroll
    for (int n = 0; n < 4; n++) {
        const int c = n * 8 + 2 * t;
        unsigned u01, u23;
        asm("cvt.rn.bf16x2.f32 %0, %1, %2;" : "=r"(u01) : "f"(d[n][1]), "f"(d[n][0]));
        asm("cvt.rn.bf16x2.f32 %0, %1, %2;" : "=r"(u23) : "f"(d[n][3]), "f"(d[n][2]));
        *reinterpret_cast<unsigned*>(&eout[(size_t)r0 * EP + c]) = u01;
        *reinterpret_cast<unsigned*>(&eout[(size_t)(r0 + 8) * EP + c]) = u23;
    }
}

// ---------------- Kernel 2: fwd/bwd scan + parallel unnorm gather ----------------
// f vector in shared (ping-pong). Matvec: 7 broadcast LDS.128 giving packed
// {f[2k],f[2k+1]} pairs + 13 fma.rn.f32x2 against pre-packed expT pairs.
static __device__ __forceinline__ float mv26p(const float* fb,
                                              const unsigned long long* eT,
                                              float &msum) {
    const ulonglong2* q = reinterpret_cast<const ulonglong2*>(fb);
    const ulonglong2 q0 = q[0], q1 = q[1], q2 = q[2], q3 = q[3],
                     q4 = q[4], q5 = q[5], q6 = q[6];
    unsigned long long a0 = 0, a1 = 0, a2 = 0, a3 = 0;
    ffma2(a0, q0.x, eT[0]);  ffma2(a1, q0.y, eT[1]);
    ffma2(a2, q1.x, eT[2]);  ffma2(a3, q1.y, eT[3]);
    ffma2(a0, q2.x, eT[4]);  ffma2(a1, q2.y, eT[5]);
    ffma2(a2, q3.x, eT[6]);  ffma2(a3, q3.y, eT[7]);
    ffma2(a0, q4.x, eT[8]);  ffma2(a1, q4.y, eT[9]);
    ffma2(a2, q5.x, eT[10]); ffma2(a3, q5.y, eT[11]);
    ffma2(a0, q6.x, eT[12]);
    fadd2(a0, a1); fadd2(a2, a3); fadd2(a0, a2);
    float lo, hi;
    asm("mov.b64 {%0, %1}, %2;" : "=f"(lo), "=f"(hi) : "l"(a0));
    msum = lo + hi;
    return msum;
}

__global__ void __launch_bounds__(192) scan_kernel(const int* __restrict__ labels,
                                                   const float* __restrict__ T) {
    __shared__ __align__(16) float fbuf[4][2][32];
    const int warp = threadIdx.x >> 5;
    const int lane = threadIdx.x & 31;
    const unsigned FULL = 0xffffffffu;

    if (warp >= 4) {
        // unnorm gather: fully parallel over positions
        const int s = blockIdx.x * 2 + (warp - 4);
        const int* __restrict__ lab = labels + s * Mv;
        const __nv_bfloat16* __restrict__ eb = g_e + (size_t)s * Mv * EP;
        float un = 0.0f;
#pragma unroll 4
        for (int k = 0; k < 32; k++) {
            const int i = k * 32 + lane;
            const int y = __ldg(&lab[i]);
            float v = __bfloat162float(eb[(size_t)i * EP + y]);
            if (i < Mv - 1)
                v += __ldg(&T[y * Nv + __ldg(&lab[i + 1])]);
            un += v;
        }
#pragma unroll
        for (int o = 16; o; o >>= 1) un += __shfl_xor_sync(FULL, un, o);
        if (lane == 0) g_u[s] = un;
        return;
    }

    const int s   = blockIdx.x * 2 + (warp >> 1);
    const int dir = warp & 1;
    const __nv_bfloat16* __restrict__ eseq = g_e + (size_t)s * Mv * EP + lane;
    float* const fb0 = fbuf[warp][0];
    float* const fb1 = fbuf[warp][1];

    unsigned long long expT2[13];
    __nv_bfloat16 ep[8];
    float carry = 1.0f;
    int   eAcc = 0;

    if (dir == 0) {
        // forward: f_i = expE_i * (expT^T f_{i-1}); i=1..512; keep pre-emission msum
#pragma unroll
        for (int k = 0; k < 13; k++)
            expT2[k] = (lane < Nv)
                ? packf2(__expf(__ldg(&T[(2 * k) * Nv + lane])),
                         __expf(__ldg(&T[(2 * k + 1) * Nv + lane])))
                : 0ull;

        const float e0 = __bfloat162float(eseq[0]);
        fb0[lane] = (lane < Nv) ? __expf(e0) : 0.0f;
        __syncwarp();
#pragma unroll
        for (int k = 0; k < 8; k++) ep[k] = eseq[(size_t)(1 + k) * EP];

        int p = 0;
        float msum = 0.0f;
        for (int gi = 0; gi < 64; gi++) {
#pragma unroll
            for (int j = 0; j < 8; j++) {
                const int i = 1 + gi * 8 + j;
                const float ee = __bfloat162float(ep[j]);
                ep[j] = eseq[(size_t)(i + 8) * EP];
                const float expE = __expf(ee) * carry;
                carry = 1.0f;
                const float* src = p ? fb1 : fb0;
                float*       dst = p ? fb0 : fb1;
                const float fn = mv26p(src, expT2, msum) * expE;
                dst[lane] = fn;
                __syncwarp();
                p ^= 1;
                if (j == 7 && gi != 63) {
                    const unsigned mb = __reduce_max_sync(FULL, __float_as_uint(fn));
                    const unsigned pb = mb & 0x7f800000u;
                    carry = __uint_as_float(0x7f000000u - pb);   // exact 2^(127-E)
                    eAcc += (int)(pb >> 23) - 127;
                }
            }
        }
        g_pF[s * EP + lane] = msum;                          // pre-emission u_512
        if (lane == 0) g_sF[s] = (float)eAcc * 0.6931471805599453f;
    } else {
        // backward (h-form): h_1023 = expE_1023; h_i = expE_i*(expT h_{i+1}); i=1022..512
#pragma unroll
        for (int k = 0; k < 13; k++)
            expT2[k] = (lane < Nv)
                ? packf2(__expf(__ldg(&T[lane * Nv + 2 * k])),
                         __expf(__ldg(&T[lane * Nv + 2 * k + 1])))
                : 0ull;

        const float e1023 = __bfloat162float(eseq[(size_t)1023 * EP]);
        fb0[lane] = (lane < Nv) ? __expf(e1023) : 0.0f;
        __syncwarp();
#pragma unroll
        for (int k = 0; k < 8; k++) ep[k] = eseq[(size_t)(1022 - k) * EP];

        int p = 0;
        float h = 0.0f, msum;
        // prologue: 7 steps, i = 1022..1016 (slots 0..6)
#pragma unroll
        for (int j = 0; j < 7; j++) {
            const int i = 1022 - j;
            const float ee = __bfloat162float(ep[j]);
            ep[j] = eseq[(size_t)(i - 8) * EP];
            const float expE = __expf(ee);
            const float* src = p ? fb1 : fb0;
            float*       dst = p ? fb0 : fb1;
            h = mv26p(src, expT2, msum) * expE;
            dst[lane] = h;
            __syncwarp();
            p ^= 1;
        }
        {
            const unsigned mb = __reduce_max_sync(FULL, __float_as_uint(h));
            const unsigned pb = mb & 0x7f800000u;
            carry = __uint_as_float(0x7f000000u - pb);
            eAcc += (int)(pb >> 23) - 127;
        }
        // 63 groups of 8: i = 1015..512
        for (int gi = 0; gi < 63; gi++) {
#pragma unroll
            for (int j = 0; j < 8; j++) {
                const int i = 1015 - gi * 8 - j;
                const int sl = (j + 7) & 7;
                const float ee = __bfloat162float(ep[sl]);
                ep[sl] = eseq[(size_t)(i - 8) * EP];
                const float expE = __expf(ee) * carry;
                carry = 1.0f;
                const float* src = p ? fb1 : fb0;
                float*       dst = p ? fb0 : fb1;
                h = mv26p(src, expT2, msum) * expE;
                dst[lane] = h;
                __syncwarp();
                p ^= 1;
                if (j == 7 && gi != 62) {
                    const unsigned mb = __reduce_max_sync(FULL, __float_as_uint(h));
                    const unsigned pb = mb & 0x7f800000u;
                    carry = __uint_as_float(0x7f000000u - pb);
                    eAcc += (int)(pb >> 23) - 127;
                }
            }
        }
        g_pB[s * EP + lane] = h;                             // h_512
        if (lane == 0) g_sB[s] = (float)eAcc * 0.6931471805599453f;
    }
}

// ---------------- Kernel 3: combine ----------------
__global__ void __launch_bounds__(256) combine_kernel(float* __restrict__ out) {
    __shared__ float red[256];
    const int s = threadIdx.x;

    float z = 0.0f;
#pragma unroll
    for (int b = 0; b < Nv; b++)
        z += g_pF[s * EP + b] * g_pB[s * EP + b];

    red[s] = g_u[s] - (logf(z) + g_sF[s] + g_sB[s]);
    __syncthreads();
#pragma unroll
    for (int o = 128; o; o >>= 1) {
        if (s < o) red[s] += red[s + o];
        __syncthreads();
    }
    if (s == 0) out[0] = red[0] * (1.0f / Bv);
}

// ---------------- entry point ----------------
extern "C" void kernel_launch(void* const* d_in, const int* in_sizes, int n_in,
                              void* d_out, int out_size) {
    const float* X      = (const float*)d_in[0];
    const int*   labels = (const int*)  d_in[1];
    const float* W      = (const float*)d_in[2];
    const float* T      = (const float*)d_in[3];
    float* out = (float*)d_out;

    emis_kernel<<<(Bv * Mv) / 128, 256>>>(X, W);
    scan_kernel<<<Bv / 2, 192>>>(labels, T);
    combine_kernel<<<1, 256>>>(out);
}